// round 16
// baseline (speedup 1.0000x reference)
#include <cuda_runtime.h>

#define S 2048
#define B 64
#define H 8
#define KK 12
#define NPOS 11
#define TBL 4096   // 1<<KK

// Scratch (__device__ globals; no allocations allowed).
__device__ unsigned long long g_tokmask[S]; // 64 token bits per row
__device__ uint4 g_AQ4[S];                  // per s: 8 x u16 = (h<<12) + addr_q
__device__ uint4 g_AK4[S];                  // per s: 8 x u16 = addr_k
__device__ uint4 g_AP4[S];                  // per rel: 8 x u16 = addr_p
__device__ uint4 g_tbw4[H * TBL / 32 / 4];  // bit table: word i, bit j = head_table[i*32+j]

// ---------------------------------------------------------------------------
// Prep: 512 blocks x 128 threads. One warp per row s (ballot mask; lanes 0..7
// compute per-head partial addresses — the three groups partition the 12
// bits, so aq+ak+ap <= 4095). Threads 0..1 of each block each build one bit-
// table word from 8 independent float4 loads.
__global__ void __launch_bounds__(128) k_prep(
        const int* __restrict__ tokens,
        const int* __restrict__ conn_heads,
        const float* __restrict__ head_table) {
    int tid = threadIdx.x;
    int lane = tid & 31;
    int gw = blockIdx.x * 4 + (tid >> 5);    // row index, 0..2047

    int t0 = tokens[gw * B + lane];
    int t1 = tokens[gw * B + 32 + lane];
    unsigned lo = __ballot_sync(0xffffffffu, t0 != 0);
    unsigned hi = __ballot_sync(0xffffffffu, t1 != 0);
    unsigned long long tm = (unsigned long long)lo | ((unsigned long long)hi << 32);
    if (lane == 0) g_tokmask[gw] = tm;

    if (lane < H) {
        int h = lane;
        int aq = 0, ak = 0, ap = 0;
#pragma unroll
        for (int j = 0; j < KK; j++) {
            int c = __ldg(&conn_heads[h * KK + j]);
            int p2 = 1 << (KK - 1 - j);
            if (c < B)          aq += (int)((tm >> c) & 1ull) * p2;
            else if (c < 2 * B) ak += (int)((tm >> (c - B)) & 1ull) * p2;
            else                ap += ((gw >> (NPOS - 1 - (c - 2 * B))) & 1) * p2;
        }
        int i = gw * 8 + h;
        ((unsigned short*)g_AQ4)[i] = (unsigned short)((h << 12) + aq);
        ((unsigned short*)g_AK4)[i] = (unsigned short)ak;
        ((unsigned short*)g_AP4)[i] = (unsigned short)ap;
    }

    if (tid < 2) {                            // 2 table words per block
        int wi = blockIdx.x * 2 + tid;        // 0..1023
        const float4* ht4 = (const float4*)head_table;
        unsigned w = 0;
#pragma unroll
        for (int r = 0; r < 8; r++) {
            float4 f = __ldg(&ht4[wi * 8 + r]);
            w |= (unsigned)(f.x != 0.0f) << (r * 4);
            w |= (unsigned)(f.y != 0.0f) << (r * 4 + 1);
            w |= (unsigned)(f.z != 0.0f) << (r * 4 + 2);
            w |= (unsigned)(f.w != 0.0f) << (r * 4 + 3);
        }
        ((unsigned*)g_tbw4)[wi] = w;
    }
}

// ---------------------------------------------------------------------------
// Main: each block handles rows bid and 2047-bid (balanced pair), 4KB bit
// table staged once. Barrier-free drift scan: warp w owns k=it*256+w*32+lane.
// Early exit via per-row shared s_minhit = min known k with vote==H
// (atomicMin by the hitting warp). A warp stops only when its next chunk
// start exceeds s_minhit, so every k below the smallest hit is scanned by
// its owner -> max over enc=(v<<11)|(2047-k) is exactly (max vote, first
// index). Over-scan past the hit is harmless (order-insensitive max).
// kc=min(k,q) clamp keeps lanes uniform (dup of k=q cannot change the max).
__global__ void __launch_bounds__(256) k_main(
        const int* __restrict__ conn_v,
        const float* __restrict__ table_v,
        float* __restrict__ out) {
    __shared__ unsigned s_tb[H * TBL / 32];   // 1024 words = 4 KB
    __shared__ int s_red[2][8];
    __shared__ int s_best[2];
    __shared__ int s_minhit[2];

    int tid = threadIdx.x;
    int lane = tid & 31, wid = tid >> 5;

    ((uint4*)s_tb)[tid] = g_tbw4[tid];        // 256 uint4 = whole table
    if (tid < 2) s_minhit[tid] = S;           // "no hit known"
    __syncthreads();

    int qa0 = blockIdx.x, qa1 = S - 1 - blockIdx.x;

#pragma unroll
    for (int r = 0; r < 2; r++) {
        int q = r ? qa1 : qa0;
        uint4 aq = g_AQ4[q];
        int best = -1;

        for (int k0 = wid * 32; k0 <= q; k0 += 256) {
            // Stop only when ALL remaining owned keys exceed the smallest
            // known hit (fresh read each iteration).
            if (k0 > *(volatile int*)&s_minhit[r]) break;
            int kc = min(k0 + lane, q);
            uint4 ak = __ldg(&g_AK4[kc]);
            uint4 ap = __ldg(&g_AP4[q - kc]);
            // packed u16 adds: (h<<12)+(aq+ak+ap) <= 32767 per lane, no carry
            unsigned wx = ak.x + ap.x + aq.x;
            unsigned wy = ak.y + ap.y + aq.y;
            unsigned wz = ak.z + ap.z + aq.z;
            unsigned ww = ak.w + ap.w + aq.w;
            // bit lookup: word = addr16>>5 (h<<12 -> region h<<7), bit = addr16&31
            int v  = (s_tb[(wx & 0xFFFFu) >> 5] >> (wx & 31)) & 1;
            v += (s_tb[wx >> 21] >> ((wx >> 16) & 31)) & 1;
            v += (s_tb[(wy & 0xFFFFu) >> 5] >> (wy & 31)) & 1;
            v += (s_tb[wy >> 21] >> ((wy >> 16) & 31)) & 1;
            v += (s_tb[(wz & 0xFFFFu) >> 5] >> (wz & 31)) & 1;
            v += (s_tb[wz >> 21] >> ((wz >> 16) & 31)) & 1;
            v += (s_tb[(ww & 0xFFFFu) >> 5] >> (ww & 31)) & 1;
            v += (s_tb[ww >> 21] >> ((ww >> 16) & 31)) & 1;
            best = max(best, (v << 11) | (2047 - kc));
            unsigned bal = __ballot_sync(0xffffffffu, v == H);
            if (bal) {
                // Smallest hitting k in this warp; publish and stop (our
                // remaining keys are all larger).
                if (lane == 0) atomicMin(&s_minhit[r], k0 + (__ffs(bal) - 1));
                break;
            }
        }

        best = __reduce_max_sync(0xffffffffu, best);
        if (lane == 0) s_red[r][wid] = best;
        // no barrier: next row uses its own minhit/red slots
    }

    __syncthreads();
    if (tid < 16) {                           // 2 segments of 8 lanes
        int r = tid >> 3;
        int m = s_red[r][tid & 7];
#pragma unroll
        for (int off = 4; off; off >>= 1)
            m = max(m, __shfl_xor_sync(0xffffu, m, off, 8));
        if ((tid & 7) == 0) s_best[r] = m;
    }
    __syncthreads();

    {   // Parallel tails: threads 0-63 -> row 0, threads 128-191 -> row 1.
        int r = tid >> 7;
        int b = tid & 127;
        if (b < B) {
            int q = r ? qa1 : qa0;
            int m = s_best[r];
            int bv = m >> 11;
            int bk = 2047 - (m & 2047);
            float o = 0.0f;
            if (bv > 0) {
                unsigned long long msk = g_tokmask[bk];
                int addr = 0;
#pragma unroll
                for (int j = 0; j < KK; j++) {
                    int c = __ldg(&conn_v[b * KK + j]);
                    addr += (int)((msk >> c) & 1ull) << (KK - 1 - j);
                }
                o = __ldg(&table_v[b * TBL + addr]);
            }
            out[q * B + b] = o;
        }
    }
}

// ---------------------------------------------------------------------------
extern "C" void kernel_launch(void* const* d_in, const int* in_sizes, int n_in,
                              void* d_out, int out_size) {
    const int*   tokens     = (const int*)d_in[0];
    const int*   conn_heads = (const int*)d_in[1];
    const float* head_table = (const float*)d_in[2];
    const int*   conn_v     = (const int*)d_in[3];
    const float* table_v    = (const float*)d_in[4];
    float* out = (float*)d_out;

    k_prep<<<S / 4, 128>>>(tokens, conn_heads, head_table);
    k_main<<<S / 2, 256>>>(conn_v, table_v, out);
}